// round 4
// baseline (speedup 1.0000x reference)
#include <cuda_runtime.h>
#include <cstdint>
#include <cstddef>

#define MAXN 100000
#define MPAD 100096
#define NI   1024
#define Q1   16256.0f          // 127*128

#define BM   128
#define BN   128
#define BK   64                 // int8 per chunk
#define NCH  (NI / BK)          // 16
#define NSTG 3

#define ROW_B   80              // 64 data + 16 pad (16B aligned, ldmatrix conflict-free)
#define TILE_B  (128 * ROW_B)   // 10240
#define OFF_AHI 0
#define OFF_ALO (1 * TILE_B)
#define OFF_BHI (2 * TILE_B)
#define OFF_BLO (3 * TILE_B)
#define STAGE_B (4 * TILE_B)    // 40960
#define DYN_SMEM (NSTG * STAGE_B)

// ---------------------------------------------------------------- scratch
__device__ int8_t g_Xhi[(size_t)MPAD * NI];   // zero-init: rows >= M stay 0
__device__ int8_t g_Xlo[(size_t)MPAD * NI];
__device__ float  g_sX [MPAD];
__device__ int8_t g_Whi[(size_t)NI * NI];
__device__ int8_t g_Wlo[(size_t)NI * NI];
__device__ float  g_sW [NI];
__device__ float  g_bufH[(size_t)MPAD * NI];

// ---------------------------------------------------------------- PTX utils
__device__ __forceinline__ uint32_t smem_u32(const void* p)
{
    uint32_t a;
    asm("{ .reg .u64 t; cvta.to.shared.u64 t, %1; cvt.u32.u64 %0, t; }"
        : "=r"(a) : "l"(p));
    return a;
}

#define LDSM_X4(r, addr)                                                        \
    asm volatile("ldmatrix.sync.aligned.m8n8.x4.shared.b16 {%0,%1,%2,%3}, [%4];"\
        : "=r"((r)[0]), "=r"((r)[1]), "=r"((r)[2]), "=r"((r)[3]) : "r"(addr))

__device__ __forceinline__ void imma(int32_t* c, const uint32_t* a,
                                     uint32_t b0, uint32_t b1)
{
    asm volatile(
        "mma.sync.aligned.m16n8k32.row.col.s32.s8.s8.s32 "
        "{%0,%1,%2,%3}, {%4,%5,%6,%7}, {%8,%9}, {%0,%1,%2,%3};\n"
        : "+r"(c[0]), "+r"(c[1]), "+r"(c[2]), "+r"(c[3])
        : "r"(a[0]), "r"(a[1]), "r"(a[2]), "r"(a[3]), "r"(b0), "r"(b1));
}

// ---------------------------------------------------------------- reductions
// 1024-thread block: sum1/sum2
__device__ __forceinline__ void block_stats(float v, float* red, float& mu, float& rstd)
{
    float s1 = v, s2 = v * v;
    #pragma unroll
    for (int off = 16; off > 0; off >>= 1) {
        s1 += __shfl_xor_sync(0xffffffffu, s1, off);
        s2 += __shfl_xor_sync(0xffffffffu, s2, off);
    }
    int wid = threadIdx.x >> 5, lane = threadIdx.x & 31;
    if (lane == 0) { red[wid] = s1; red[32 + wid] = s2; }
    __syncthreads();
    if (wid == 0) {
        s1 = red[lane]; s2 = red[32 + lane];
        #pragma unroll
        for (int off = 16; off > 0; off >>= 1) {
            s1 += __shfl_xor_sync(0xffffffffu, s1, off);
            s2 += __shfl_xor_sync(0xffffffffu, s2, off);
        }
        if (lane == 0) { red[0] = s1; red[32] = s2; }
    }
    __syncthreads();
    float mean = red[0] * (1.0f / NI);
    float var  = red[32] * (1.0f / NI) - mean * mean;
    mu = mean;
    rstd = rsqrtf(var + 1e-5f);
}

// 1024-thread block amax (sync at entry: red may still be read by block_stats tail)
__device__ __forceinline__ float block_amax(float v, float* red)
{
    __syncthreads();
    float a = fabsf(v);
    #pragma unroll
    for (int off = 16; off > 0; off >>= 1)
        a = fmaxf(a, __shfl_xor_sync(0xffffffffu, a, off));
    int wid = threadIdx.x >> 5, lane = threadIdx.x & 31;
    if (lane == 0) red[wid] = a;
    __syncthreads();
    if (wid == 0) {
        a = red[lane];
        #pragma unroll
        for (int off = 16; off > 0; off >>= 1)
            a = fmaxf(a, __shfl_xor_sync(0xffffffffu, a, off));
        if (lane == 0) red[0] = a;
    }
    __syncthreads();
    return red[0];
}

__device__ __forceinline__ void quant_store(size_t idx, float y, float inv)
{
    float q  = y * inv;
    float hi = rintf(q * 0.0078125f);
    hi = fminf(fmaxf(hi, -127.f), 127.f);
    float lo = rintf(q - 128.f * hi);
    g_Xhi[idx] = (int8_t)(int)hi;
    g_Xlo[idx] = (int8_t)(int)lo;
}

// ---------------------------------------------------------------- stage 1
// Gram + sign-clamp + LN1 + lrelu + int8 hi/lo quantization
__global__ void prep_kernel(const float* __restrict__ f,
                            const float* __restrict__ gamma,
                            const float* __restrict__ beta,
                            int m)
{
    int n = blockIdx.x;
    __shared__ float sv[96];
    __shared__ float red[64];
    int t = threadIdx.x;
    if (t < 32 * m) sv[t] = f[(size_t)n * 32 * m + t];
    __syncthreads();
    int a = t >> 5, b = t & 31;
    float d = 0.f;
    #pragma unroll 3
    for (int c = 0; c < m; ++c) d += sv[a * m + c] * sv[b * m + c];
    if (d > 0.f)      d = fmaxf(d,  1e-12f);
    else if (d < 0.f) d = fminf(d, -1e-12f);
    float mu, rstd;
    block_stats(d, red, mu, rstd);
    float y = (d - mu) * rstd * gamma[t] + beta[t];
    y = (y >= 0.f) ? y : 0.01f * y;
    float amax = block_amax(y, red);
    float inv  = (amax > 0.f) ? (Q1 / amax) : 0.f;
    quant_store((size_t)n * NI + t, y, inv);
    if (t == 0) g_sX[n] = amax * (1.0f / Q1);
}

// ---------------------------------------------------------------- stage 3
// LN2 + lrelu + quantization; 256 threads x float4
__global__ void mid_ln_kernel(const float* __restrict__ gamma,
                              const float* __restrict__ beta)
{
    int n = blockIdx.x;
    int t = threadIdx.x;                 // 0..255
    __shared__ float red[24];
    const float4 d = *(const float4*)&g_bufH[(size_t)n * NI + t * 4];

    float s1 = d.x + d.y + d.z + d.w;
    float s2 = d.x * d.x + d.y * d.y + d.z * d.z + d.w * d.w;
    #pragma unroll
    for (int off = 16; off > 0; off >>= 1) {
        s1 += __shfl_xor_sync(0xffffffffu, s1, off);
        s2 += __shfl_xor_sync(0xffffffffu, s2, off);
    }
    int wid = t >> 5, lane = t & 31;
    if (lane == 0) { red[wid] = s1; red[8 + wid] = s2; }
    __syncthreads();
    if (wid == 0) {
        s1 = (lane < 8) ? red[lane] : 0.f;
        s2 = (lane < 8) ? red[8 + lane] : 0.f;
        #pragma unroll
        for (int off = 4; off > 0; off >>= 1) {
            s1 += __shfl_xor_sync(0xffffffffu, s1, off);
            s2 += __shfl_xor_sync(0xffffffffu, s2, off);
        }
        if (lane == 0) { red[0] = s1; red[8] = s2; }
    }
    __syncthreads();
    float mu   = red[0] * (1.0f / NI);
    float var  = red[8] * (1.0f / NI) - mu * mu;
    float rstd = rsqrtf(var + 1e-5f);

    const float4 gg = *(const float4*)&gamma[t * 4];
    const float4 bb = *(const float4*)&beta[t * 4];
    float y0 = (d.x - mu) * rstd * gg.x + bb.x; y0 = (y0 >= 0.f) ? y0 : 0.01f * y0;
    float y1 = (d.y - mu) * rstd * gg.y + bb.y; y1 = (y1 >= 0.f) ? y1 : 0.01f * y1;
    float y2 = (d.z - mu) * rstd * gg.z + bb.z; y2 = (y2 >= 0.f) ? y2 : 0.01f * y2;
    float y3 = (d.w - mu) * rstd * gg.w + bb.w; y3 = (y3 >= 0.f) ? y3 : 0.01f * y3;

    __syncthreads();
    float a = fmaxf(fmaxf(fabsf(y0), fabsf(y1)), fmaxf(fabsf(y2), fabsf(y3)));
    #pragma unroll
    for (int off = 16; off > 0; off >>= 1)
        a = fmaxf(a, __shfl_xor_sync(0xffffffffu, a, off));
    if (lane == 0) red[16 + wid] = a;
    __syncthreads();
    if (wid == 0) {
        a = (lane < 8) ? red[16 + lane] : 0.f;
        #pragma unroll
        for (int off = 4; off > 0; off >>= 1)
            a = fmaxf(a, __shfl_xor_sync(0xffffffffu, a, off));
        if (lane == 0) red[16] = a;
    }
    __syncthreads();
    float amax = red[16];
    float inv  = (amax > 0.f) ? (Q1 / amax) : 0.f;

    size_t base = (size_t)n * NI + t * 4;
    quant_store(base + 0, y0, inv);
    quant_store(base + 1, y1, inv);
    quant_store(base + 2, y2, inv);
    quant_store(base + 3, y3, inv);
    if (t == 0) g_sX[n] = amax * (1.0f / Q1);
}

// ---------------------------------------------------------------- W quant
__global__ void wquant_kernel(const float* __restrict__ W)
{
    int r = blockIdx.x;
    int t = threadIdx.x;
    __shared__ float red[64];
    float w = W[(size_t)r * NI + t];

    float a = fabsf(w);
    #pragma unroll
    for (int off = 16; off > 0; off >>= 1)
        a = fmaxf(a, __shfl_xor_sync(0xffffffffu, a, off));
    int wid = t >> 5, lane = t & 31;
    if (lane == 0) red[wid] = a;
    __syncthreads();
    if (wid == 0) {
        a = red[lane];
        #pragma unroll
        for (int off = 16; off > 0; off >>= 1)
            a = fmaxf(a, __shfl_xor_sync(0xffffffffu, a, off));
        if (lane == 0) red[0] = a;
    }
    __syncthreads();
    float amax = red[0];
    float inv  = (amax > 0.f) ? (Q1 / amax) : 0.f;

    float q  = w * inv;
    float hi = rintf(q * 0.0078125f);
    hi = fminf(fmaxf(hi, -127.f), 127.f);
    float lo = rintf(q - 128.f * hi);
    g_Whi[(size_t)r * NI + t] = (int8_t)(int)hi;
    g_Wlo[(size_t)r * NI + t] = (int8_t)(int)lo;
    if (t == 0) g_sW[r] = amax * (1.0f / Q1);
}

// ---------------------------------------------------------------- int8 GEMM
// C[M,1024] = sA sB (128^2 hh + 128 (hl+lh)) (+bias); IMMA m16n8k32.
// 128x128x64 tile, 8 warps (warp 64x32), 3-stage cp.async pipeline.
__device__ __forceinline__ void load_stage(uint32_t sbase, int bm, int bn,
                                           int k0, int tid)
{
    #pragma unroll 8
    for (int i = 0; i < 8; ++i) {
        int idx  = tid + i * 256;          // 0..2047
        int tile = idx >> 9;               // 0..3
        int r    = (idx >> 2) & 127;
        int c    = (idx & 3) * 16;         // byte offset in 64B row
        const int8_t* src;
        if (tile < 2)
            src = ((tile == 0) ? g_Xhi : g_Xlo) + (size_t)(bm + r) * NI + k0 + c;
        else
            src = ((tile == 2) ? g_Whi : g_Wlo) + (size_t)(bn + r) * NI + k0 + c;
        uint32_t dst = sbase + tile * TILE_B + r * ROW_B + c;
        asm volatile("cp.async.cg.shared.global [%0], [%1], 16;"
                     :: "r"(dst), "l"(src) : "memory");
    }
    asm volatile("cp.async.commit_group;" ::: "memory");
}

__global__ __launch_bounds__(256)
void gemm_i8_kernel(const float* __restrict__ bias, int M)
{
    extern __shared__ __align__(128) char dyn[];

    const int tid    = threadIdx.x;
    const int wid    = tid >> 5;
    const int lane   = tid & 31;
    const int warp_m = wid >> 2;           // 0..1
    const int warp_n = wid & 3;            // 0..3
    const int bn     = blockIdx.x * BN;
    const int bm     = blockIdx.y * BM;

    const uint32_t sdyn = smem_u32(dyn);

    // int8-k32 ldmatrix lane offsets (bytes)
    const uint32_t laneA = (uint32_t)(((lane & 7) + ((lane >> 3) & 1) * 8) * ROW_B
                                      + (lane >> 4) * 16);
    const uint32_t laneB = (uint32_t)(((lane & 7) + (lane >> 4) * 8) * ROW_B
                                      + ((lane >> 3) & 1) * 16);
    const uint32_t aWarp = (uint32_t)(warp_m * 64 * ROW_B);
    const uint32_t bWarp = (uint32_t)(warp_n * 32 * ROW_B);

    int32_t hh[4][4][4], cx[4][4][4];
    #pragma unroll
    for (int i = 0; i < 4; ++i)
        #pragma unroll
        for (int j = 0; j < 4; ++j)
            #pragma unroll
            for (int k = 0; k < 4; ++k) { hh[i][j][k] = 0; cx[i][j][k] = 0; }

    load_stage(sdyn + 0 * STAGE_B, bm, bn, 0 * BK, tid);
    load_stage(sdyn + 1 * STAGE_B, bm, bn, 1 * BK, tid);
    load_stage(sdyn + 2 * STAGE_B, bm, bn, 2 * BK, tid);

    int stage = 0;
    for (int c = 0; c < NCH; ++c) {
        asm volatile("cp.async.wait_group 2;" ::: "memory");
        __syncthreads();
        const uint32_t sb = sdyn + stage * STAGE_B;

        #pragma unroll
        for (int kg = 0; kg < 2; ++kg) {       // two k32 groups
            const uint32_t kb = kg * 32;
            uint32_t ah[4][4], al[4][4], bh[2][4], bl[2][4];
            #pragma unroll
            for (int mt = 0; mt < 4; ++mt) {
                uint32_t o = aWarp + mt * (16 * ROW_B) + laneA + kb;
                LDSM_X4(ah[mt], sb + OFF_AHI + o);
                LDSM_X4(al[mt], sb + OFF_ALO + o);
            }
            #pragma unroll
            for (int n2 = 0; n2 < 2; ++n2) {
                uint32_t o = bWarp + n2 * (16 * ROW_B) + laneB + kb;
                LDSM_X4(bh[n2], sb + OFF_BHI + o);
                LDSM_X4(bl[n2], sb + OFF_BLO + o);
            }
            #pragma unroll
            for (int mt = 0; mt < 4; ++mt)
                #pragma unroll
                for (int nt = 0; nt < 4; ++nt) {
                    const int n2 = nt >> 1, ns = (nt & 1) * 2;
                    imma(hh[mt][nt], ah[mt], bh[n2][ns], bh[n2][ns + 1]);
                    imma(cx[mt][nt], al[mt], bh[n2][ns], bh[n2][ns + 1]);
                    imma(cx[mt][nt], ah[mt], bl[n2][ns], bl[n2][ns + 1]);
                }
        }
        __syncthreads();
        if (c + NSTG < NCH)
            load_stage(sb, bm, bn, (c + NSTG) * BK, tid);
        stage = (stage + 1) % NSTG;
    }

    // ---- epilogue: combine with scales, add bias, store fp32
    const int g  = lane >> 2;
    const int tg = lane & 3;
    #pragma unroll
    for (int mt = 0; mt < 4; ++mt) {
        int row0 = bm + warp_m * 64 + mt * 16 + g;
        float sa0 = g_sX[row0] * 128.f;
        float sa1 = g_sX[row0 + 8 < MPAD ? row0 + 8 : row0] * 128.f;
        #pragma unroll
        for (int nt = 0; nt < 4; ++nt) {
            int col = bn + warp_n * 32 + nt * 8 + tg * 2;
            float sb0 = __ldg(&g_sW[col]);
            float sb1 = __ldg(&g_sW[col + 1]);
            float b0 = bias ? __ldg(&bias[col])     : 0.f;
            float b1 = bias ? __ldg(&bias[col + 1]) : 0.f;
            if (row0 < M) {
                float t0 = fmaf(128.f, __int2float_rn(hh[mt][nt][0]),
                                __int2float_rn(cx[mt][nt][0]));
                float t1 = fmaf(128.f, __int2float_rn(hh[mt][nt][1]),
                                __int2float_rn(cx[mt][nt][1]));
                float2 v = make_float2(sa0 * sb0 * t0 + b0, sa0 * sb1 * t1 + b1);
                *(float2*)&g_bufH[(size_t)row0 * NI + col] = v;
            }
            if (row0 + 8 < M) {
                float t2 = fmaf(128.f, __int2float_rn(hh[mt][nt][2]),
                                __int2float_rn(cx[mt][nt][2]));
                float t3 = fmaf(128.f, __int2float_rn(hh[mt][nt][3]),
                                __int2float_rn(cx[mt][nt][3]));
                float2 v = make_float2(sa1 * sb0 * t2 + b0, sa1 * sb1 * t3 + b1);
                *(float2*)&g_bufH[(size_t)(row0 + 8) * NI + col] = v;
            }
        }
    }
}

// ---------------------------------------------------------------- stage 5
__global__ void post_kernel(const float* __restrict__ f,
                            float* __restrict__ out,
                            int m)
{
    int n = blockIdx.x;
    __shared__ float sv[96];
    int t = threadIdx.x;
    if (t < 32 * m) sv[t] = f[(size_t)n * 32 * m + t];
    __syncthreads();
    int o = t >> 5, lane = t & 31;
    float l = g_bufH[(size_t)n * NI + o * 32 + lane];
    float mx = l;
    #pragma unroll
    for (int off = 16; off > 0; off >>= 1)
        mx = fmaxf(mx, __shfl_xor_sync(0xffffffffu, mx, off));
    float e = expf(l - mx);
    float s = e;
    #pragma unroll
    for (int off = 16; off > 0; off >>= 1)
        s += __shfl_xor_sync(0xffffffffu, s, off);
    float attn = e / s;
    #pragma unroll 3
    for (int c = 0; c < m; ++c) {
        float p = attn * sv[lane * m + c];
        #pragma unroll
        for (int off = 16; off > 0; off >>= 1)
            p += __shfl_xor_sync(0xffffffffu, p, off);
        if (lane == 0) out[(size_t)n * 32 * m + o * m + c] = p;
    }
}

// ---------------------------------------------------------------- launch
static void run_type(const float* f, void* const* prm, float* out, int N, int m)
{
    const float* g1    = (const float*)prm[0];
    const float* b1    = (const float*)prm[1];
    const float* w1    = (const float*)prm[2];
    const float* g2    = (const float*)prm[3];
    const float* b2    = (const float*)prm[4];
    const float* w2    = (const float*)prm[5];
    const float* bias2 = (const float*)prm[6];

    dim3 ggrid(NI / BN, (N + BM - 1) / BM);   // n fastest -> A reuse in L2

    prep_kernel<<<N, 1024>>>(f, g1, b1, m);
    wquant_kernel<<<NI, 1024>>>(w1);
    gemm_i8_kernel<<<ggrid, 256, DYN_SMEM>>>(nullptr, N);
    mid_ln_kernel<<<N, 256>>>(g2, b2);
    wquant_kernel<<<NI, 1024>>>(w2);
    gemm_i8_kernel<<<ggrid, 256, DYN_SMEM>>>(bias2, N);
    post_kernel<<<N, 1024>>>(f, out, m);
}

extern "C" void kernel_launch(void* const* d_in, const int* in_sizes, int n_in,
                              void* d_out, int out_size)
{
    cudaFuncSetAttribute(gemm_i8_kernel,
                         cudaFuncAttributeMaxDynamicSharedMemorySize, DYN_SMEM);

    const float* f0 = (const float*)d_in[0];
    const float* f1 = (const float*)d_in[1];
    int N0 = in_sizes[0] / 32;
    int N1 = in_sizes[1] / 96;
    if (N0 > MAXN) N0 = MAXN;
    if (N1 > MAXN) N1 = MAXN;
    float* out = (float*)d_out;

    run_type(f0, d_in + 2, out, N0, 1);
    run_type(f1, d_in + 9, out + (size_t)N0 * 32, N1, 3);
}

// round 5
// speedup vs baseline: 2.8321x; 2.8321x over previous
#include <cuda_runtime.h>
#include <cuda_fp16.h>
#include <cstdint>
#include <cstddef>

#define MAXN 100000
#define MPAD 100096
#define NI   1024

#define BM   128
#define BN   128
#define BK   32
#define NCH  (NI / BK)          // 32
#define NSTG 3

// smem tile: [128 rows][40 fp16] (32 data + 8 pad) = 10240 B
#define TILE_B   10240
#define ROW_B    80
#define OFF_AHI  0
#define OFF_ALO  (1 * TILE_B)
#define OFF_BH   (2 * TILE_B)
#define STAGE_B  (3 * TILE_B)          // 30720
#define DYN_SMEM (NSTG * STAGE_B)      // 92160

// ---------------------------------------------------------------- scratch
__device__ __half g_Xhi[(size_t)MPAD * NI];   // zero-init: rows >= M stay 0
__device__ __half g_Xlo[(size_t)MPAD * NI];
__device__ __half g_Wh [(size_t)NI * NI];
__device__ float  g_bufH[(size_t)MPAD * NI];

// ---------------------------------------------------------------- PTX utils
__device__ __forceinline__ uint32_t smem_u32(const void* p)
{
    uint32_t a;
    asm("{ .reg .u64 t; cvta.to.shared.u64 t, %1; cvt.u32.u64 %0, t; }"
        : "=r"(a) : "l"(p));
    return a;
}

#define LDSM_X4(r, addr)                                                        \
    asm volatile("ldmatrix.sync.aligned.m8n8.x4.shared.b16 {%0,%1,%2,%3}, [%4];"\
        : "=r"((r)[0]), "=r"((r)[1]), "=r"((r)[2]), "=r"((r)[3]) : "r"(addr))

__device__ __forceinline__ void mma_f16(float* c, const uint32_t* a,
                                        const uint32_t b0, const uint32_t b1)
{
    asm volatile(
        "mma.sync.aligned.m16n8k16.row.col.f32.f16.f16.f32 "
        "{%0,%1,%2,%3}, {%4,%5,%6,%7}, {%8,%9}, {%0,%1,%2,%3};\n"
        : "+f"(c[0]), "+f"(c[1]), "+f"(c[2]), "+f"(c[3])
        : "r"(a[0]), "r"(a[1]), "r"(a[2]), "r"(a[3]), "r"(b0), "r"(b1));
}

// ---------------------------------------------------------------- LN stats
__device__ __forceinline__ void block_stats(float v, float* red, float& mu, float& rstd)
{
    float s1 = v, s2 = v * v;
    #pragma unroll
    for (int off = 16; off > 0; off >>= 1) {
        s1 += __shfl_xor_sync(0xffffffffu, s1, off);
        s2 += __shfl_xor_sync(0xffffffffu, s2, off);
    }
    int wid = threadIdx.x >> 5, lane = threadIdx.x & 31;
    if (lane == 0) { red[wid] = s1; red[32 + wid] = s2; }
    __syncthreads();
    if (wid == 0) {
        s1 = red[lane]; s2 = red[32 + lane];
        #pragma unroll
        for (int off = 16; off > 0; off >>= 1) {
            s1 += __shfl_xor_sync(0xffffffffu, s1, off);
            s2 += __shfl_xor_sync(0xffffffffu, s2, off);
        }
        if (lane == 0) { red[0] = s1; red[32] = s2; }
    }
    __syncthreads();
    float mean = red[0] * (1.0f / NI);
    float var  = red[32] * (1.0f / NI) - mean * mean;
    mu = mean;
    rstd = rsqrtf(var + 1e-5f);
}

__device__ __forceinline__ void split_store(size_t idx, float y)
{
    __half h = __float2half_rn(y);
    g_Xhi[idx] = h;
    g_Xlo[idx] = __float2half_rn(y - __half2float(h));
}

// ---------------------------------------------------------------- stage 1
// Gram + sign-clamp + LN1 + lrelu -> fp16 hi/lo split
__global__ void prep_kernel(const float* __restrict__ f,
                            const float* __restrict__ gamma,
                            const float* __restrict__ beta,
                            int m)
{
    int n = blockIdx.x;
    __shared__ float sv[96];
    __shared__ float red[64];
    int t = threadIdx.x;
    if (t < 32 * m) sv[t] = f[(size_t)n * 32 * m + t];
    __syncthreads();
    int a = t >> 5, b = t & 31;
    float d = 0.f;
    #pragma unroll 3
    for (int c = 0; c < m; ++c) d += sv[a * m + c] * sv[b * m + c];
    if (d > 0.f)      d = fmaxf(d,  1e-12f);
    else if (d < 0.f) d = fminf(d, -1e-12f);
    float mu, rstd;
    block_stats(d, red, mu, rstd);
    float y = (d - mu) * rstd * gamma[t] + beta[t];
    y = (y >= 0.f) ? y : 0.01f * y;
    split_store((size_t)n * NI + t, y);
}

// ---------------------------------------------------------------- stage 3
// LN2 + lrelu + fp16 split; 256 threads x float4
__global__ void mid_ln_kernel(const float* __restrict__ gamma,
                              const float* __restrict__ beta)
{
    int n = blockIdx.x;
    int t = threadIdx.x;                 // 0..255
    __shared__ float red[16];
    const float4 d = *(const float4*)&g_bufH[(size_t)n * NI + t * 4];

    float s1 = d.x + d.y + d.z + d.w;
    float s2 = d.x * d.x + d.y * d.y + d.z * d.z + d.w * d.w;
    #pragma unroll
    for (int off = 16; off > 0; off >>= 1) {
        s1 += __shfl_xor_sync(0xffffffffu, s1, off);
        s2 += __shfl_xor_sync(0xffffffffu, s2, off);
    }
    int wid = t >> 5, lane = t & 31;
    if (lane == 0) { red[wid] = s1; red[8 + wid] = s2; }
    __syncthreads();
    if (wid == 0) {
        s1 = (lane < 8) ? red[lane] : 0.f;
        s2 = (lane < 8) ? red[8 + lane] : 0.f;
        #pragma unroll
        for (int off = 4; off > 0; off >>= 1) {
            s1 += __shfl_xor_sync(0xffffffffu, s1, off);
            s2 += __shfl_xor_sync(0xffffffffu, s2, off);
        }
        if (lane == 0) { red[0] = s1; red[8] = s2; }
    }
    __syncthreads();
    float mu   = red[0] * (1.0f / NI);
    float var  = red[8] * (1.0f / NI) - mu * mu;
    float rstd = rsqrtf(var + 1e-5f);

    const float4 gg = *(const float4*)&gamma[t * 4];
    const float4 bb = *(const float4*)&beta[t * 4];
    float y0 = (d.x - mu) * rstd * gg.x + bb.x; y0 = (y0 >= 0.f) ? y0 : 0.01f * y0;
    float y1 = (d.y - mu) * rstd * gg.y + bb.y; y1 = (y1 >= 0.f) ? y1 : 0.01f * y1;
    float y2 = (d.z - mu) * rstd * gg.z + bb.z; y2 = (y2 >= 0.f) ? y2 : 0.01f * y2;
    float y3 = (d.w - mu) * rstd * gg.w + bb.w; y3 = (y3 >= 0.f) ? y3 : 0.01f * y3;

    size_t base = (size_t)n * NI + t * 4;
    __half h0 = __float2half_rn(y0), h1 = __float2half_rn(y1);
    __half h2 = __float2half_rn(y2), h3 = __float2half_rn(y3);
    __half2 hi01 = __halves2half2(h0, h1), hi23 = __halves2half2(h2, h3);
    __half2 lo01 = __halves2half2(__float2half_rn(y0 - __half2float(h0)),
                                  __float2half_rn(y1 - __half2float(h1)));
    __half2 lo23 = __halves2half2(__float2half_rn(y2 - __half2float(h2)),
                                  __float2half_rn(y3 - __half2float(h3)));
    *(__half2*)&g_Xhi[base]     = hi01;
    *(__half2*)&g_Xhi[base + 2] = hi23;
    *(__half2*)&g_Xlo[base]     = lo01;
    *(__half2*)&g_Xlo[base + 2] = lo23;
}

// ---------------------------------------------------------------- W -> fp16
__global__ void wsplit_kernel(const float* __restrict__ W)
{
    int i = blockIdx.x * 256 + threadIdx.x;
    g_Wh[i] = __float2half_rn(W[i]);
}

// ---------------------------------------------------------------- GEMM
// C[M,1024] = X @ W^T (+bias): fp16 2-product (ah*bh + al*bh), HMMA m16n8k16.
// 128x128x32 tile, 8 warps (warp 64x32), 3-stage cp.async pipeline.
__device__ __forceinline__ void load_stage(uint32_t sbase, int bm, int bn,
                                           int k0, int tid)
{
    #pragma unroll 6
    for (int i = 0; i < 6; ++i) {
        int idx  = tid + i * 256;          // 0..1535
        int tile = idx >> 9;               // 0..2
        int r    = (idx >> 2) & 127;
        int c    = (idx & 3) * 8;          // fp16 col
        const __half* src;
        if (tile == 0)      src = g_Xhi + (size_t)(bm + r) * NI + k0 + c;
        else if (tile == 1) src = g_Xlo + (size_t)(bm + r) * NI + k0 + c;
        else                src = g_Wh  + (size_t)(bn + r) * NI + k0 + c;
        uint32_t dst = sbase + tile * TILE_B + r * ROW_B + c * 2;
        asm volatile("cp.async.cg.shared.global [%0], [%1], 16;"
                     :: "r"(dst), "l"(src) : "memory");
    }
    asm volatile("cp.async.commit_group;" ::: "memory");
}

__global__ __launch_bounds__(256)
void gemm_f16_kernel(const float* __restrict__ bias, int M)
{
    extern __shared__ __align__(128) char dyn[];

    const int tid    = threadIdx.x;
    const int wid    = tid >> 5;
    const int lane   = tid & 31;
    const int warp_m = wid >> 2;           // 0..1
    const int warp_n = wid & 3;            // 0..3
    const int bn     = blockIdx.x * BN;
    const int bm     = blockIdx.y * BM;

    const uint32_t sdyn = smem_u32(dyn);

    const uint32_t laneA = (uint32_t)((lane & 15) * ROW_B + (lane >> 4) * 16);
    const uint32_t laneB = (uint32_t)(((lane & 7) + ((lane >> 4) * 8)) * ROW_B
                                      + (((lane >> 3) & 1) * 16));
    const uint32_t aWarp = (uint32_t)(warp_m * 64 * ROW_B);
    const uint32_t bWarp = (uint32_t)(warp_n * 32 * ROW_B);

    float acc[4][4][4];
    #pragma unroll
    for (int i = 0; i < 4; ++i)
        #pragma unroll
        for (int j = 0; j < 4; ++j)
            #pragma unroll
            for (int k = 0; k < 4; ++k) acc[i][j][k] = 0.f;

    load_stage(sdyn + 0 * STAGE_B, bm, bn, 0 * BK, tid);
    load_stage(sdyn + 1 * STAGE_B, bm, bn, 1 * BK, tid);
    load_stage(sdyn + 2 * STAGE_B, bm, bn, 2 * BK, tid);

    int stage = 0;
    for (int c = 0; c < NCH; ++c) {
        asm volatile("cp.async.wait_group 2;" ::: "memory");
        __syncthreads();
        const uint32_t sb = sdyn + stage * STAGE_B;

        #pragma unroll
        for (int half = 0; half < 2; ++half) {
            const uint32_t kb = half * 32;   // 16 fp16 = 32 B
            uint32_t ah[4][4], al[4][4], bh[2][4];
            #pragma unroll
            for (int mt = 0; mt < 4; ++mt) {
                uint32_t o = aWarp + mt * (16 * ROW_B) + laneA + kb;
                LDSM_X4(ah[mt], sb + OFF_AHI + o);
                LDSM_X4(al[mt], sb + OFF_ALO + o);
            }
            #pragma unroll
            for (int n2 = 0; n2 < 2; ++n2) {
                uint32_t o = bWarp + n2 * (16 * ROW_B) + laneB + kb;
                LDSM_X4(bh[n2], sb + OFF_BH + o);
            }
            #pragma unroll
            for (int mt = 0; mt < 4; ++mt)
                #pragma unroll
                for (int nt = 0; nt < 4; ++nt) {
                    const int n2 = nt >> 1, ns = (nt & 1) * 2;
                    mma_f16(acc[mt][nt], ah[mt], bh[n2][ns], bh[n2][ns + 1]);
                    mma_f16(acc[mt][nt], al[mt], bh[n2][ns], bh[n2][ns + 1]);
                }
        }
        __syncthreads();
        if (c + NSTG < NCH)
            load_stage(sb, bm, bn, (c + NSTG) * BK, tid);
        stage = (stage + 1) % NSTG;
    }

    // ---- epilogue: direct stores
    const int g  = lane >> 2;
    const int tg = lane & 3;
    #pragma unroll
    for (int mt = 0; mt < 4; ++mt) {
        int row0 = bm + warp_m * 64 + mt * 16 + g;
        #pragma unroll
        for (int nt = 0; nt < 4; ++nt) {
            int col = bn + warp_n * 32 + nt * 8 + tg * 2;
            float b0 = bias ? __ldg(&bias[col])     : 0.f;
            float b1 = bias ? __ldg(&bias[col + 1]) : 0.f;
            if (row0 < M) {
                float2 v = make_float2(acc[mt][nt][0] + b0, acc[mt][nt][1] + b1);
                *(float2*)&g_bufH[(size_t)row0 * NI + col] = v;
            }
            if (row0 + 8 < M) {
                float2 v = make_float2(acc[mt][nt][2] + b0, acc[mt][nt][3] + b1);
                *(float2*)&g_bufH[(size_t)(row0 + 8) * NI + col] = v;
            }
        }
    }
}

// ---------------------------------------------------------------- stage 5
__global__ void post_kernel(const float* __restrict__ f,
                            float* __restrict__ out,
                            int m)
{
    int n = blockIdx.x;
    __shared__ float sv[96];
    int t = threadIdx.x;
    if (t < 32 * m) sv[t] = f[(size_t)n * 32 * m + t];
    __syncthreads();
    int o = t >> 5, lane = t & 31;
    float l = g_bufH[(size_t)n * NI + o * 32 + lane];
    float mx = l;
    #pragma unroll
    for (int off = 16; off > 0; off >>= 1)
        mx = fmaxf(mx, __shfl_xor_sync(0xffffffffu, mx, off));
    float e = expf(l - mx);
    float s = e;
    #pragma unroll
    for (int off = 16; off > 0; off >>= 1)
        s += __shfl_xor_sync(0xffffffffu, s, off);
    float attn = e / s;
    #pragma unroll 3
    for (int c = 0; c < m; ++c) {
        float p = attn * sv[lane * m + c];
        #pragma unroll
        for (int off = 16; off > 0; off >>= 1)
            p += __shfl_xor_sync(0xffffffffu, p, off);
        if (lane == 0) out[(size_t)n * 32 * m + o * m + c] = p;
    }
}

// ---------------------------------------------------------------- launch
static void run_type(const float* f, void* const* prm, float* out, int N, int m)
{
    const float* g1    = (const float*)prm[0];
    const float* b1    = (const float*)prm[1];
    const float* w1    = (const float*)prm[2];
    const float* g2    = (const float*)prm[3];
    const float* b2    = (const float*)prm[4];
    const float* w2    = (const float*)prm[5];
    const float* bias2 = (const float*)prm[6];

    dim3 ggrid(NI / BN, (N + BM - 1) / BM);   // n fastest -> A reuse in L2

    prep_kernel<<<N, 1024>>>(f, g1, b1, m);
    wsplit_kernel<<<(NI * NI) / 256, 256>>>(w1);
    gemm_f16_kernel<<<ggrid, 256, DYN_SMEM>>>(nullptr, N);
    mid_ln_kernel<<<N, 256>>>(g2, b2);
    wsplit_kernel<<<(NI * NI) / 256, 256>>>(w2);
    gemm_f16_kernel<<<ggrid, 256, DYN_SMEM>>>(bias2, N);
    post_kernel<<<N, 1024>>>(f, out, m);
}

extern "C" void kernel_launch(void* const* d_in, const int* in_sizes, int n_in,
                              void* d_out, int out_size)
{
    cudaFuncSetAttribute(gemm_f16_kernel,
                         cudaFuncAttributeMaxDynamicSharedMemorySize, DYN_SMEM);

    const float* f0 = (const float*)d_in[0];
    const float* f1 = (const float*)d_in[1];
    int N0 = in_sizes[0] / 32;
    int N1 = in_sizes[1] / 96;
    if (N0 > MAXN) N0 = MAXN;
    if (N1 > MAXN) N1 = MAXN;
    float* out = (float*)d_out;

    run_type(f0, d_in + 2, out, N0, 1);
    run_type(f1, d_in + 9, out + (size_t)N0 * 32, N1, 3);
}

// round 6
// speedup vs baseline: 3.8010x; 1.3421x over previous
#include <cuda_runtime.h>
#include <cuda_fp16.h>
#include <cstdint>
#include <cstddef>

#define MAXN 100000
#define MPAD 100096
#define NI   1024

#define BM   128
#define BN   128
#define BK   32
#define NCH  (NI / BK)          // 32
#define NSTG 3

// smem tile: [128 rows][40 fp16] (32 data + 8 pad) = 10240 B
#define TILE_B   10240
#define ROW_B    80
#define OFF_A    0
#define OFF_B    (1 * TILE_B)
#define STAGE_B  (2 * TILE_B)          // 20480
#define DYN_SMEM (NSTG * STAGE_B)      // 61440

// ---------------------------------------------------------------- scratch
__device__ __half g_Xh [(size_t)MPAD * NI];   // zero-init: rows >= M stay 0
__device__ __half g_Wh [(size_t)NI * NI];
__device__ float  g_bufH[(size_t)MPAD * NI];

// ---------------------------------------------------------------- PTX utils
__device__ __forceinline__ uint32_t smem_u32(const void* p)
{
    uint32_t a;
    asm("{ .reg .u64 t; cvta.to.shared.u64 t, %1; cvt.u32.u64 %0, t; }"
        : "=r"(a) : "l"(p));
    return a;
}

#define LDSM_X4(r, addr)                                                        \
    asm volatile("ldmatrix.sync.aligned.m8n8.x4.shared.b16 {%0,%1,%2,%3}, [%4];"\
        : "=r"((r)[0]), "=r"((r)[1]), "=r"((r)[2]), "=r"((r)[3]) : "r"(addr))

__device__ __forceinline__ void mma_f16(float* c, const uint32_t* a,
                                        const uint32_t b0, const uint32_t b1)
{
    asm volatile(
        "mma.sync.aligned.m16n8k16.row.col.f32.f16.f16.f32 "
        "{%0,%1,%2,%3}, {%4,%5,%6,%7}, {%8,%9}, {%0,%1,%2,%3};\n"
        : "+f"(c[0]), "+f"(c[1]), "+f"(c[2]), "+f"(c[3])
        : "r"(a[0]), "r"(a[1]), "r"(a[2]), "r"(a[3]), "r"(b0), "r"(b1));
}

// ---------------------------------------------------------------- LN stats
__device__ __forceinline__ void block_stats(float v, float* red, float& mu, float& rstd)
{
    float s1 = v, s2 = v * v;
    #pragma unroll
    for (int off = 16; off > 0; off >>= 1) {
        s1 += __shfl_xor_sync(0xffffffffu, s1, off);
        s2 += __shfl_xor_sync(0xffffffffu, s2, off);
    }
    int wid = threadIdx.x >> 5, lane = threadIdx.x & 31;
    if (lane == 0) { red[wid] = s1; red[32 + wid] = s2; }
    __syncthreads();
    if (wid == 0) {
        s1 = red[lane]; s2 = red[32 + lane];
        #pragma unroll
        for (int off = 16; off > 0; off >>= 1) {
            s1 += __shfl_xor_sync(0xffffffffu, s1, off);
            s2 += __shfl_xor_sync(0xffffffffu, s2, off);
        }
        if (lane == 0) { red[0] = s1; red[32] = s2; }
    }
    __syncthreads();
    float mean = red[0] * (1.0f / NI);
    float var  = red[32] * (1.0f / NI) - mean * mean;
    mu = mean;
    rstd = rsqrtf(var + 1e-5f);
}

// ---------------------------------------------------------------- stage 1
// Gram + sign-clamp + LN1 + lrelu -> fp16
__global__ void prep_kernel(const float* __restrict__ f,
                            const float* __restrict__ gamma,
                            const float* __restrict__ beta,
                            int m)
{
    int n = blockIdx.x;
    __shared__ float sv[96];
    __shared__ float red[64];
    int t = threadIdx.x;
    if (t < 32 * m) sv[t] = f[(size_t)n * 32 * m + t];
    __syncthreads();
    int a = t >> 5, b = t & 31;
    float d = 0.f;
    #pragma unroll 3
    for (int c = 0; c < m; ++c) d += sv[a * m + c] * sv[b * m + c];
    if (d > 0.f)      d = fmaxf(d,  1e-12f);
    else if (d < 0.f) d = fminf(d, -1e-12f);
    float mu, rstd;
    block_stats(d, red, mu, rstd);
    float y = (d - mu) * rstd * gamma[t] + beta[t];
    y = (y >= 0.f) ? y : 0.01f * y;
    g_Xh[(size_t)n * NI + t] = __float2half_rn(y);
}

// ---------------------------------------------------------------- stage 3
// LN2 + lrelu -> fp16; 256 threads x float4
__global__ void mid_ln_kernel(const float* __restrict__ gamma,
                              const float* __restrict__ beta)
{
    int n = blockIdx.x;
    int t = threadIdx.x;                 // 0..255
    __shared__ float red[16];
    const float4 d = *(const float4*)&g_bufH[(size_t)n * NI + t * 4];

    float s1 = d.x + d.y + d.z + d.w;
    float s2 = d.x * d.x + d.y * d.y + d.z * d.z + d.w * d.w;
    #pragma unroll
    for (int off = 16; off > 0; off >>= 1) {
        s1 += __shfl_xor_sync(0xffffffffu, s1, off);
        s2 += __shfl_xor_sync(0xffffffffu, s2, off);
    }
    int wid = t >> 5, lane = t & 31;
    if (lane == 0) { red[wid] = s1; red[8 + wid] = s2; }
    __syncthreads();
    if (wid == 0) {
        s1 = (lane < 8) ? red[lane] : 0.f;
        s2 = (lane < 8) ? red[8 + lane] : 0.f;
        #pragma unroll
        for (int off = 4; off > 0; off >>= 1) {
            s1 += __shfl_xor_sync(0xffffffffu, s1, off);
            s2 += __shfl_xor_sync(0xffffffffu, s2, off);
        }
        if (lane == 0) { red[0] = s1; red[8] = s2; }
    }
    __syncthreads();
    float mu   = red[0] * (1.0f / NI);
    float var  = red[8] * (1.0f / NI) - mu * mu;
    float rstd = rsqrtf(var + 1e-5f);

    const float4 gg = *(const float4*)&gamma[t * 4];
    const float4 bb = *(const float4*)&beta[t * 4];
    float y0 = (d.x - mu) * rstd * gg.x + bb.x; y0 = (y0 >= 0.f) ? y0 : 0.01f * y0;
    float y1 = (d.y - mu) * rstd * gg.y + bb.y; y1 = (y1 >= 0.f) ? y1 : 0.01f * y1;
    float y2 = (d.z - mu) * rstd * gg.z + bb.z; y2 = (y2 >= 0.f) ? y2 : 0.01f * y2;
    float y3 = (d.w - mu) * rstd * gg.w + bb.w; y3 = (y3 >= 0.f) ? y3 : 0.01f * y3;

    size_t base = (size_t)n * NI + t * 4;
    __half2 h01 = __halves2half2(__float2half_rn(y0), __float2half_rn(y1));
    __half2 h23 = __halves2half2(__float2half_rn(y2), __float2half_rn(y3));
    *(__half2*)&g_Xh[base]     = h01;
    *(__half2*)&g_Xh[base + 2] = h23;
}

// ---------------------------------------------------------------- W -> fp16
__global__ void wsplit_kernel(const float* __restrict__ W)
{
    int i = blockIdx.x * 256 + threadIdx.x;
    g_Wh[i] = __float2half_rn(W[i]);
}

// ---------------------------------------------------------------- GEMM
// C[M,1024] = X @ W^T (+bias): single fp16 product, HMMA m16n8k16.
// 128x128x32 tile, 8 warps (warp 64x32), 3-stage cp.async pipeline.
__device__ __forceinline__ void load_stage(uint32_t sbase, int bm, int bn,
                                           int k0, int tid)
{
    #pragma unroll 4
    for (int i = 0; i < 4; ++i) {
        int idx  = tid + i * 256;          // 0..1023
        int tile = idx >> 9;               // 0..1
        int r    = (idx >> 2) & 127;
        int c    = (idx & 3) * 8;          // fp16 col
        const __half* src = (tile == 0)
            ? g_Xh + (size_t)(bm + r) * NI + k0 + c
            : g_Wh + (size_t)(bn + r) * NI + k0 + c;
        uint32_t dst = sbase + tile * TILE_B + r * ROW_B + c * 2;
        asm volatile("cp.async.cg.shared.global [%0], [%1], 16;"
                     :: "r"(dst), "l"(src) : "memory");
    }
    asm volatile("cp.async.commit_group;" ::: "memory");
}

__global__ __launch_bounds__(256)
void gemm_f16_kernel(const float* __restrict__ bias, int M)
{
    extern __shared__ __align__(128) char dyn[];

    const int tid    = threadIdx.x;
    const int wid    = tid >> 5;
    const int lane   = tid & 31;
    const int warp_m = wid >> 2;           // 0..1
    const int warp_n = wid & 3;            // 0..3
    const int bn     = blockIdx.x * BN;
    const int bm     = blockIdx.y * BM;

    const uint32_t sdyn = smem_u32(dyn);

    const uint32_t laneA = (uint32_t)((lane & 15) * ROW_B + (lane >> 4) * 16);
    const uint32_t laneB = (uint32_t)(((lane & 7) + ((lane >> 4) * 8)) * ROW_B
                                      + (((lane >> 3) & 1) * 16));
    const uint32_t aWarp = (uint32_t)(warp_m * 64 * ROW_B);
    const uint32_t bWarp = (uint32_t)(warp_n * 32 * ROW_B);

    float acc[4][4][4];
    #pragma unroll
    for (int i = 0; i < 4; ++i)
        #pragma unroll
        for (int j = 0; j < 4; ++j)
            #pragma unroll
            for (int k = 0; k < 4; ++k) acc[i][j][k] = 0.f;

    load_stage(sdyn + 0 * STAGE_B, bm, bn, 0 * BK, tid);
    load_stage(sdyn + 1 * STAGE_B, bm, bn, 1 * BK, tid);
    load_stage(sdyn + 2 * STAGE_B, bm, bn, 2 * BK, tid);

    int stage = 0;
    for (int c = 0; c < NCH; ++c) {
        asm volatile("cp.async.wait_group 2;" ::: "memory");
        __syncthreads();
        const uint32_t sb = sdyn + stage * STAGE_B;

        #pragma unroll
        for (int half = 0; half < 2; ++half) {
            const uint32_t kb = half * 32;   // 16 fp16 = 32 B
            uint32_t ah[4][4], bh[2][4];
            #pragma unroll
            for (int mt = 0; mt < 4; ++mt) {
                uint32_t o = aWarp + mt * (16 * ROW_B) + laneA + kb;
                LDSM_X4(ah[mt], sb + OFF_A + o);
            }
            #pragma unroll
            for (int n2 = 0; n2 < 2; ++n2) {
                uint32_t o = bWarp + n2 * (16 * ROW_B) + laneB + kb;
                LDSM_X4(bh[n2], sb + OFF_B + o);
            }
            #pragma unroll
            for (int mt = 0; mt < 4; ++mt)
                #pragma unroll
                for (int nt = 0; nt < 4; ++nt) {
                    const int n2 = nt >> 1, ns = (nt & 1) * 2;
                    mma_f16(acc[mt][nt], ah[mt], bh[n2][ns], bh[n2][ns + 1]);
                }
        }
        __syncthreads();
        if (c + NSTG < NCH)
            load_stage(sb, bm, bn, (c + NSTG) * BK, tid);
        stage = (stage + 1) % NSTG;
    }

    // ---- epilogue: direct stores
    const int g  = lane >> 2;
    const int tg = lane & 3;
    #pragma unroll
    for (int mt = 0; mt < 4; ++mt) {
        int row0 = bm + warp_m * 64 + mt * 16 + g;
        #pragma unroll
        for (int nt = 0; nt < 4; ++nt) {
            int col = bn + warp_n * 32 + nt * 8 + tg * 2;
            float b0 = bias ? __ldg(&bias[col])     : 0.f;
            float b1 = bias ? __ldg(&bias[col + 1]) : 0.f;
            if (row0 < M) {
                float2 v = make_float2(acc[mt][nt][0] + b0, acc[mt][nt][1] + b1);
                *(float2*)&g_bufH[(size_t)row0 * NI + col] = v;
            }
            if (row0 + 8 < M) {
                float2 v = make_float2(acc[mt][nt][2] + b0, acc[mt][nt][3] + b1);
                *(float2*)&g_bufH[(size_t)(row0 + 8) * NI + col] = v;
            }
        }
    }
}

// ---------------------------------------------------------------- stage 5
__global__ void post_kernel(const float* __restrict__ f,
                            float* __restrict__ out,
                            int m)
{
    int n = blockIdx.x;
    __shared__ float sv[96];
    int t = threadIdx.x;
    if (t < 32 * m) sv[t] = f[(size_t)n * 32 * m + t];
    __syncthreads();
    int o = t >> 5, lane = t & 31;
    float l = g_bufH[(size_t)n * NI + o * 32 + lane];
    float mx = l;
    #pragma unroll
    for (int off = 16; off > 0; off >>= 1)
        mx = fmaxf(mx, __shfl_xor_sync(0xffffffffu, mx, off));
    float e = expf(l - mx);
    float s = e;
    #pragma unroll
    for (int off = 16; off > 0; off >>= 1)
        s += __shfl_xor_sync(0xffffffffu, s, off);
    float attn = e / s;
    #pragma unroll 3
    for (int c = 0; c < m; ++c) {
        float p = attn * sv[lane * m + c];
        #pragma unroll
        for (int off = 16; off > 0; off >>= 1)
            p += __shfl_xor_sync(0xffffffffu, p, off);
        if (lane == 0) out[(size_t)n * 32 * m + o * m + c] = p;
    }
}

// ---------------------------------------------------------------- launch
static void run_type(const float* f, void* const* prm, float* out, int N, int m)
{
    const float* g1    = (const float*)prm[0];
    const float* b1    = (const float*)prm[1];
    const float* w1    = (const float*)prm[2];
    const float* g2    = (const float*)prm[3];
    const float* b2    = (const float*)prm[4];
    const float* w2    = (const float*)prm[5];
    const float* bias2 = (const float*)prm[6];

    dim3 ggrid(NI / BN, (N + BM - 1) / BM);   // n fastest -> A reuse in L2

    prep_kernel<<<N, 1024>>>(f, g1, b1, m);
    wsplit_kernel<<<(NI * NI) / 256, 256>>>(w1);
    gemm_f16_kernel<<<ggrid, 256, DYN_SMEM>>>(nullptr, N);
    mid_ln_kernel<<<N, 256>>>(g2, b2);
    wsplit_kernel<<<(NI * NI) / 256, 256>>>(w2);
    gemm_f16_kernel<<<ggrid, 256, DYN_SMEM>>>(bias2, N);
    post_kernel<<<N, 1024>>>(f, out, m);
}

extern "C" void kernel_launch(void* const* d_in, const int* in_sizes, int n_in,
                              void* d_out, int out_size)
{
    cudaFuncSetAttribute(gemm_f16_kernel,
                         cudaFuncAttributeMaxDynamicSharedMemorySize, DYN_SMEM);

    const float* f0 = (const float*)d_in[0];
    const float* f1 = (const float*)d_in[1];
    int N0 = in_sizes[0] / 32;
    int N1 = in_sizes[1] / 96;
    if (N0 > MAXN) N0 = MAXN;
    if (N1 > MAXN) N1 = MAXN;
    float* out = (float*)d_out;

    run_type(f0, d_in + 2, out, N0, 1);
    run_type(f1, d_in + 9, out + (size_t)N0 * 32, N1, 3);
}

// round 7
// speedup vs baseline: 6.4208x; 1.6892x over previous
#include <cuda_runtime.h>
#include <cuda_fp16.h>
#include <cstdint>
#include <cstddef>

#define MAXN 100000
#define MPAD 100096
#define NI   1024

#define BM   128
#define BN   128
#define BK   64
#define NCH  (NI / BK)          // 16
#define NSTG 2

// smem tile: [128 rows][72 fp16] (64 data + 8 pad) = 18432 B
#define ROW_B    144
#define TILE_B   (128 * ROW_B)         // 18432
#define OFF_A    0
#define OFF_B    (1 * TILE_B)
#define STAGE_B  (2 * TILE_B)          // 36864
#define DYN_SMEM (NSTG * STAGE_B)      // 73728

// ---------------------------------------------------------------- scratch
__device__ __half g_Xh [(size_t)MPAD * NI];   // zero-init: rows >= M stay 0
__device__ __half g_Wh [(size_t)NI * NI];
__device__ float  g_bufH[(size_t)MPAD * NI];

// ---------------------------------------------------------------- PTX utils
__device__ __forceinline__ uint32_t smem_u32(const void* p)
{
    uint32_t a;
    asm("{ .reg .u64 t; cvta.to.shared.u64 t, %1; cvt.u32.u64 %0, t; }"
        : "=r"(a) : "l"(p));
    return a;
}

#define LDSM_X4(r, addr)                                                        \
    asm volatile("ldmatrix.sync.aligned.m8n8.x4.shared.b16 {%0,%1,%2,%3}, [%4];"\
        : "=r"((r)[0]), "=r"((r)[1]), "=r"((r)[2]), "=r"((r)[3]) : "r"(addr))

__device__ __forceinline__ void mma_f16(float* c, const uint32_t* a,
                                        const uint32_t b0, const uint32_t b1)
{
    asm volatile(
        "mma.sync.aligned.m16n8k16.row.col.f32.f16.f16.f32 "
        "{%0,%1,%2,%3}, {%4,%5,%6,%7}, {%8,%9}, {%0,%1,%2,%3};\n"
        : "+f"(c[0]), "+f"(c[1]), "+f"(c[2]), "+f"(c[3])
        : "r"(a[0]), "r"(a[1]), "r"(a[2]), "r"(a[3]), "r"(b0), "r"(b1));
}

// ---------------------------------------------------------------- 256-thr stats
// each thread holds 4 values; returns mu, rstd over all 1024
__device__ __forceinline__ void stats256(float s1, float s2, float* red,
                                         float& mu, float& rstd)
{
    #pragma unroll
    for (int off = 16; off > 0; off >>= 1) {
        s1 += __shfl_xor_sync(0xffffffffu, s1, off);
        s2 += __shfl_xor_sync(0xffffffffu, s2, off);
    }
    int wid = threadIdx.x >> 5, lane = threadIdx.x & 31;
    if (lane == 0) { red[wid] = s1; red[8 + wid] = s2; }
    __syncthreads();
    if (wid == 0) {
        s1 = (lane < 8) ? red[lane] : 0.f;
        s2 = (lane < 8) ? red[8 + lane] : 0.f;
        #pragma unroll
        for (int off = 4; off > 0; off >>= 1) {
            s1 += __shfl_xor_sync(0xffffffffu, s1, off);
            s2 += __shfl_xor_sync(0xffffffffu, s2, off);
        }
        if (lane == 0) { red[0] = s1; red[8] = s2; }
    }
    __syncthreads();
    mu   = red[0] * (1.0f / NI);
    float var = red[8] * (1.0f / NI) - mu * mu;
    rstd = rsqrtf(var + 1e-5f);
}

// ---------------------------------------------------------------- stage 1
// Gram + sign-clamp + LN1 + lrelu -> fp16; 256 threads x 4 entries
__global__ void prep_kernel(const float* __restrict__ f,
                            const float* __restrict__ gamma,
                            const float* __restrict__ beta,
                            int m)
{
    int n = blockIdx.x;
    __shared__ float sv[96];
    __shared__ float red[16];
    int t = threadIdx.x;                       // 0..255
    if (t < 32 * m) sv[t] = f[(size_t)n * 32 * m + t];
    __syncthreads();

    const int a  = t >> 3;                     // row (0..31)
    const int b0 = (t & 7) * 4;                // first col of 4
    float y[4];
    #pragma unroll
    for (int i = 0; i < 4; ++i) {
        float d = 0.f;
        #pragma unroll 3
        for (int c = 0; c < m; ++c) d += sv[a * m + c] * sv[(b0 + i) * m + c];
        if (d > 0.f)      d = fmaxf(d,  1e-12f);
        else if (d < 0.f) d = fminf(d, -1e-12f);
        y[i] = d;
    }
    float s1 = y[0] + y[1] + y[2] + y[3];
    float s2 = y[0]*y[0] + y[1]*y[1] + y[2]*y[2] + y[3]*y[3];
    float mu, rstd;
    stats256(s1, s2, red, mu, rstd);

    size_t base = (size_t)n * NI + t * 4;
    const float4 gg = *(const float4*)&gamma[t * 4];
    const float4 bb = *(const float4*)&beta[t * 4];
    float v0 = (y[0]-mu)*rstd*gg.x + bb.x; v0 = (v0>=0.f)?v0:0.01f*v0;
    float v1 = (y[1]-mu)*rstd*gg.y + bb.y; v1 = (v1>=0.f)?v1:0.01f*v1;
    float v2 = (y[2]-mu)*rstd*gg.z + bb.z; v2 = (v2>=0.f)?v2:0.01f*v2;
    float v3 = (y[3]-mu)*rstd*gg.w + bb.w; v3 = (v3>=0.f)?v3:0.01f*v3;
    *(__half2*)&g_Xh[base]     = __halves2half2(__float2half_rn(v0), __float2half_rn(v1));
    *(__half2*)&g_Xh[base + 2] = __halves2half2(__float2half_rn(v2), __float2half_rn(v3));
}

// ---------------------------------------------------------------- stage 3
// LN2 + lrelu -> fp16; 256 threads x float4
__global__ void mid_ln_kernel(const float* __restrict__ gamma,
                              const float* __restrict__ beta)
{
    int n = blockIdx.x;
    int t = threadIdx.x;
    __shared__ float red[16];
    const float4 d = *(const float4*)&g_bufH[(size_t)n * NI + t * 4];

    float s1 = d.x + d.y + d.z + d.w;
    float s2 = d.x*d.x + d.y*d.y + d.z*d.z + d.w*d.w;
    float mu, rstd;
    stats256(s1, s2, red, mu, rstd);

    const float4 gg = *(const float4*)&gamma[t * 4];
    const float4 bb = *(const float4*)&beta[t * 4];
    float y0 = (d.x-mu)*rstd*gg.x + bb.x; y0 = (y0>=0.f)?y0:0.01f*y0;
    float y1 = (d.y-mu)*rstd*gg.y + bb.y; y1 = (y1>=0.f)?y1:0.01f*y1;
    float y2 = (d.z-mu)*rstd*gg.z + bb.z; y2 = (y2>=0.f)?y2:0.01f*y2;
    float y3 = (d.w-mu)*rstd*gg.w + bb.w; y3 = (y3>=0.f)?y3:0.01f*y3;

    size_t base = (size_t)n * NI + t * 4;
    *(__half2*)&g_Xh[base]     = __halves2half2(__float2half_rn(y0), __float2half_rn(y1));
    *(__half2*)&g_Xh[base + 2] = __halves2half2(__float2half_rn(y2), __float2half_rn(y3));
}

// ---------------------------------------------------------------- W -> fp16
__global__ void wsplit_kernel(const float* __restrict__ W)
{
    int i = blockIdx.x * 256 + threadIdx.x;
    g_Wh[i] = __float2half_rn(W[i]);
}

// ---------------------------------------------------------------- GEMM
// C[M,1024] = X @ W^T (+bias): fp16 HMMA m16n8k16.
// 128x128x64 tile, 8 warps (warp 64x32), 2-stage cp.async pipeline.
__device__ __forceinline__ void load_stage(uint32_t sbase, int bm, int bn,
                                           int k0, int tid)
{
    #pragma unroll 8
    for (int i = 0; i < 8; ++i) {
        int idx  = tid + i * 256;          // 0..2047
        int tile = idx >> 10;              // 0..1
        int r    = (idx >> 3) & 127;
        int c    = (idx & 7) * 8;          // fp16 col
        const __half* src = (tile == 0)
            ? g_Xh + (size_t)(bm + r) * NI + k0 + c
            : g_Wh + (size_t)(bn + r) * NI + k0 + c;
        uint32_t dst = sbase + tile * TILE_B + r * ROW_B + c * 2;
        asm volatile("cp.async.cg.shared.global [%0], [%1], 16;"
                     :: "r"(dst), "l"(src) : "memory");
    }
    asm volatile("cp.async.commit_group;" ::: "memory");
}

__global__ __launch_bounds__(256)
void gemm_f16_kernel(const float* __restrict__ bias, int M)
{
    extern __shared__ __align__(128) char dyn[];

    const int tid    = threadIdx.x;
    const int wid    = tid >> 5;
    const int lane   = tid & 31;
    const int warp_m = wid >> 2;           // 0..1
    const int warp_n = wid & 3;            // 0..3
    const int bn     = blockIdx.x * BN;
    const int bm     = blockIdx.y * BM;

    const uint32_t sdyn = smem_u32(dyn);

    const uint32_t laneA = (uint32_t)((lane & 15) * ROW_B + (lane >> 4) * 16);
    const uint32_t laneB = (uint32_t)(((lane & 7) + ((lane >> 4) * 8)) * ROW_B
                                      + (((lane >> 3) & 1) * 16));
    const uint32_t aWarp = (uint32_t)(warp_m * 64 * ROW_B);
    const uint32_t bWarp = (uint32_t)(warp_n * 32 * ROW_B);

    float acc[4][4][4];
    #pragma unroll
    for (int i = 0; i < 4; ++i)
        #pragma unroll
        for (int j = 0; j < 4; ++j)
            #pragma unroll
            for (int k = 0; k < 4; ++k) acc[i][j][k] = 0.f;

    load_stage(sdyn + 0 * STAGE_B, bm, bn, 0 * BK, tid);
    load_stage(sdyn + 1 * STAGE_B, bm, bn, 1 * BK, tid);

    for (int c = 0; c < NCH; ++c) {
        asm volatile("cp.async.wait_group 1;" ::: "memory");
        __syncthreads();
        const uint32_t sb = sdyn + (c & 1) * STAGE_B;

        #pragma unroll
        for (int kg = 0; kg < 4; ++kg) {
            const uint32_t kb = kg * 32;     // 16 fp16 = 32 B
            uint32_t ah[4][4], bh[2][4];
            #pragma unroll
            for (int mt = 0; mt < 4; ++mt) {
                uint32_t o = aWarp + mt * (16 * ROW_B) + laneA + kb;
                LDSM_X4(ah[mt], sb + OFF_A + o);
            }
            #pragma unroll
            for (int n2 = 0; n2 < 2; ++n2) {
                uint32_t o = bWarp + n2 * (16 * ROW_B) + laneB + kb;
                LDSM_X4(bh[n2], sb + OFF_B + o);
            }
            #pragma unroll
            for (int mt = 0; mt < 4; ++mt)
                #pragma unroll
                for (int nt = 0; nt < 4; ++nt) {
                    const int n2 = nt >> 1, ns = (nt & 1) * 2;
                    mma_f16(acc[mt][nt], ah[mt], bh[n2][ns], bh[n2][ns + 1]);
                }
        }
        __syncthreads();
        if (c + NSTG < NCH)
            load_stage(sb, bm, bn, (c + NSTG) * BK, tid);
    }

    // ---- epilogue: direct stores
    const int g  = lane >> 2;
    const int tg = lane & 3;
    #pragma unroll
    for (int mt = 0; mt < 4; ++mt) {
        int row0 = bm + warp_m * 64 + mt * 16 + g;
        #pragma unroll
        for (int nt = 0; nt < 4; ++nt) {
            int col = bn + warp_n * 32 + nt * 8 + tg * 2;
            float b0 = bias ? __ldg(&bias[col])     : 0.f;
            float b1 = bias ? __ldg(&bias[col + 1]) : 0.f;
            if (row0 < M) {
                float2 v = make_float2(acc[mt][nt][0] + b0, acc[mt][nt][1] + b1);
                *(float2*)&g_bufH[(size_t)row0 * NI + col] = v;
            }
            if (row0 + 8 < M) {
                float2 v = make_float2(acc[mt][nt][2] + b0, acc[mt][nt][3] + b1);
                *(float2*)&g_bufH[(size_t)(row0 + 8) * NI + col] = v;
            }
        }
    }
}

// ---------------------------------------------------------------- stage 5
// one warp = one node; lane = output channel. Serial register softmax.
__global__ void post_kernel(const float* __restrict__ f,
                            float* __restrict__ out,
                            int m, int N)
{
    __shared__ float sv[8][96];
    const int w    = threadIdx.x >> 5;           // warp in block (0..7)
    const int lane = threadIdx.x & 31;
    const int n    = blockIdx.x * 8 + w;
    if (n >= N) return;

    // load v for this node into smem (32*m floats)
    for (int i = lane; i < 32 * m; i += 32)
        sv[w][i] = f[(size_t)n * 32 * m + i];
    __syncwarp();

    // lane reads its logits row (channel = lane): 32 contiguous floats
    float l[32];
    const float4* lp = (const float4*)&g_bufH[(size_t)n * NI + lane * 32];
    #pragma unroll
    for (int q = 0; q < 8; ++q) {
        float4 v4 = lp[q];
        l[q*4+0] = v4.x; l[q*4+1] = v4.y; l[q*4+2] = v4.z; l[q*4+3] = v4.w;
    }
    float mx = l[0];
    #pragma unroll
    for (int b = 1; b < 32; ++b) mx = fmaxf(mx, l[b]);
    float s = 0.f;
    #pragma unroll
    for (int b = 0; b < 32; ++b) { l[b] = __expf(l[b] - mx); s += l[b]; }
    float inv = 1.0f / s;

    // out[n][lane][c] = (1/s) * sum_b e_b * v[b][c]
    #pragma unroll 3
    for (int c = 0; c < m; ++c) {
        float acc = 0.f;
        #pragma unroll
        for (int b = 0; b < 32; ++b) acc += l[b] * sv[w][b * m + c];
        out[((size_t)n * 32 + lane) * m + c] = acc * inv;
    }
}

// ---------------------------------------------------------------- launch
static void run_type(const float* f, void* const* prm, float* out, int N, int m)
{
    const float* g1    = (const float*)prm[0];
    const float* b1    = (const float*)prm[1];
    const float* w1    = (const float*)prm[2];
    const float* g2    = (const float*)prm[3];
    const float* b2    = (const float*)prm[4];
    const float* w2    = (const float*)prm[5];
    const float* bias2 = (const float*)prm[6];

    dim3 ggrid(NI / BN, (N + BM - 1) / BM);   // n fastest -> A reuse in L2

    prep_kernel<<<N, 256>>>(f, g1, b1, m);
    wsplit_kernel<<<(NI * NI) / 256, 256>>>(w1);
    gemm_f16_kernel<<<ggrid, 256, DYN_SMEM>>>(nullptr, N);
    mid_ln_kernel<<<N, 256>>>(g2, b2);
    wsplit_kernel<<<(NI * NI) / 256, 256>>>(w2);
    gemm_f16_kernel<<<ggrid, 256, DYN_SMEM>>>(bias2, N);
    post_kernel<<<(N + 7) / 8, 256>>>(f, out, m, N);
}

extern "C" void kernel_launch(void* const* d_in, const int* in_sizes, int n_in,
                              void* d_out, int out_size)
{
    cudaFuncSetAttribute(gemm_f16_kernel,
                         cudaFuncAttributeMaxDynamicSharedMemorySize, DYN_SMEM);

    const float* f0 = (const float*)d_in[0];
    const float* f1 = (const float*)d_in[1];
    int N0 = in_sizes[0] / 32;
    int N1 = in_sizes[1] / 96;
    if (N0 > MAXN) N0 = MAXN;
    if (N1 > MAXN) N1 = MAXN;
    float* out = (float*)d_out;

    run_type(f0, d_in + 2, out, N0, 1);
    run_type(f1, d_in + 9, out + (size_t)N0 * 32, N1, 3);
}

// round 8
// speedup vs baseline: 6.6527x; 1.0361x over previous
#include <cuda_runtime.h>
#include <cuda_fp16.h>
#include <cstdint>
#include <cstddef>

#define MAXN 100000
#define MPAD 100096
#define NI   1024

#define BM   128
#define BN   128
#define BK   64
#define NCH  (NI / BK)          // 16
#define NSTG 2

// smem tile: [128 rows][72 fp16] (64 data + 8 pad) = 18432 B
#define ROW_B    144
#define TILE_B   (128 * ROW_B)         // 18432
#define OFF_A    0
#define OFF_B    (1 * TILE_B)
#define STAGE_B  (2 * TILE_B)          // 36864
#define DYN_SMEM (NSTG * STAGE_B)      // 73728

// ---------------------------------------------------------------- scratch
// two buffers: one per type chain (chains run concurrently on two streams)
__device__ __half g_Xh [2][(size_t)MPAD * NI];  // zero-init: rows >= M stay 0
__device__ __half g_Wh [2][(size_t)NI * NI];
__device__ float  g_bufH[2][(size_t)MPAD * NI];

// ---------------------------------------------------------------- PTX utils
__device__ __forceinline__ uint32_t smem_u32(const void* p)
{
    uint32_t a;
    asm("{ .reg .u64 t; cvta.to.shared.u64 t, %1; cvt.u32.u64 %0, t; }"
        : "=r"(a) : "l"(p));
    return a;
}

#define LDSM_X4(r, addr)                                                        \
    asm volatile("ldmatrix.sync.aligned.m8n8.x4.shared.b16 {%0,%1,%2,%3}, [%4];"\
        : "=r"((r)[0]), "=r"((r)[1]), "=r"((r)[2]), "=r"((r)[3]) : "r"(addr))

__device__ __forceinline__ void mma_f16(float* c, const uint32_t* a,
                                        const uint32_t b0, const uint32_t b1)
{
    asm volatile(
        "mma.sync.aligned.m16n8k16.row.col.f32.f16.f16.f32 "
        "{%0,%1,%2,%3}, {%4,%5,%6,%7}, {%8,%9}, {%0,%1,%2,%3};\n"
        : "+f"(c[0]), "+f"(c[1]), "+f"(c[2]), "+f"(c[3])
        : "r"(a[0]), "r"(a[1]), "r"(a[2]), "r"(a[3]), "r"(b0), "r"(b1));
}

// ---------------------------------------------------------------- 256-thr stats
__device__ __forceinline__ void stats256(float s1, float s2, float* red,
                                         float& mu, float& rstd)
{
    #pragma unroll
    for (int off = 16; off > 0; off >>= 1) {
        s1 += __shfl_xor_sync(0xffffffffu, s1, off);
        s2 += __shfl_xor_sync(0xffffffffu, s2, off);
    }
    int wid = threadIdx.x >> 5, lane = threadIdx.x & 31;
    if (lane == 0) { red[wid] = s1; red[8 + wid] = s2; }
    __syncthreads();
    if (wid == 0) {
        s1 = (lane < 8) ? red[lane] : 0.f;
        s2 = (lane < 8) ? red[8 + lane] : 0.f;
        #pragma unroll
        for (int off = 4; off > 0; off >>= 1) {
            s1 += __shfl_xor_sync(0xffffffffu, s1, off);
            s2 += __shfl_xor_sync(0xffffffffu, s2, off);
        }
        if (lane == 0) { red[0] = s1; red[8] = s2; }
    }
    __syncthreads();
    mu   = red[0] * (1.0f / NI);
    float var = red[8] * (1.0f / NI) - mu * mu;
    rstd = rsqrtf(var + 1e-5f);
}

// ---------------------------------------------------------------- stage 1
// Gram + sign-clamp + LN1 + lrelu -> fp16; 256 threads x 4 entries
__global__ void prep_kernel(const float* __restrict__ f,
                            const float* __restrict__ gamma,
                            const float* __restrict__ beta,
                            int m, int which)
{
    __half* __restrict__ Xh = g_Xh[which];
    int n = blockIdx.x;
    __shared__ float sv[96];
    __shared__ float red[16];
    int t = threadIdx.x;                       // 0..255
    if (t < 32 * m) sv[t] = f[(size_t)n * 32 * m + t];
    __syncthreads();

    const int a  = t >> 3;                     // row (0..31)
    const int b0 = (t & 7) * 4;                // first col of 4
    float y[4];
    #pragma unroll
    for (int i = 0; i < 4; ++i) {
        float d = 0.f;
        #pragma unroll 3
        for (int c = 0; c < m; ++c) d += sv[a * m + c] * sv[(b0 + i) * m + c];
        if (d > 0.f)      d = fmaxf(d,  1e-12f);
        else if (d < 0.f) d = fminf(d, -1e-12f);
        y[i] = d;
    }
    float s1 = y[0] + y[1] + y[2] + y[3];
    float s2 = y[0]*y[0] + y[1]*y[1] + y[2]*y[2] + y[3]*y[3];
    float mu, rstd;
    stats256(s1, s2, red, mu, rstd);

    size_t base = (size_t)n * NI + t * 4;
    const float4 gg = *(const float4*)&gamma[t * 4];
    const float4 bb = *(const float4*)&beta[t * 4];
    float v0 = (y[0]-mu)*rstd*gg.x + bb.x; v0 = (v0>=0.f)?v0:0.01f*v0;
    float v1 = (y[1]-mu)*rstd*gg.y + bb.y; v1 = (v1>=0.f)?v1:0.01f*v1;
    float v2 = (y[2]-mu)*rstd*gg.z + bb.z; v2 = (v2>=0.f)?v2:0.01f*v2;
    float v3 = (y[3]-mu)*rstd*gg.w + bb.w; v3 = (v3>=0.f)?v3:0.01f*v3;
    *(__half2*)&Xh[base]     = __halves2half2(__float2half_rn(v0), __float2half_rn(v1));
    *(__half2*)&Xh[base + 2] = __halves2half2(__float2half_rn(v2), __float2half_rn(v3));
}

// ---------------------------------------------------------------- stage 3
// LN2 + lrelu -> fp16; 256 threads x float4
__global__ void mid_ln_kernel(const float* __restrict__ gamma,
                              const float* __restrict__ beta,
                              int which)
{
    const float* __restrict__ H  = g_bufH[which];
    __half* __restrict__      Xh = g_Xh[which];
    int n = blockIdx.x;
    int t = threadIdx.x;
    __shared__ float red[16];
    const float4 d = *(const float4*)&H[(size_t)n * NI + t * 4];

    float s1 = d.x + d.y + d.z + d.w;
    float s2 = d.x*d.x + d.y*d.y + d.z*d.z + d.w*d.w;
    float mu, rstd;
    stats256(s1, s2, red, mu, rstd);

    const float4 gg = *(const float4*)&gamma[t * 4];
    const float4 bb = *(const float4*)&beta[t * 4];
    float y0 = (d.x-mu)*rstd*gg.x + bb.x; y0 = (y0>=0.f)?y0:0.01f*y0;
    float y1 = (d.y-mu)*rstd*gg.y + bb.y; y1 = (y1>=0.f)?y1:0.01f*y1;
    float y2 = (d.z-mu)*rstd*gg.z + bb.z; y2 = (y2>=0.f)?y2:0.01f*y2;
    float y3 = (d.w-mu)*rstd*gg.w + bb.w; y3 = (y3>=0.f)?y3:0.01f*y3;

    size_t base = (size_t)n * NI + t * 4;
    *(__half2*)&Xh[base]     = __halves2half2(__float2half_rn(y0), __float2half_rn(y1));
    *(__half2*)&Xh[base + 2] = __halves2half2(__float2half_rn(y2), __float2half_rn(y3));
}

// ---------------------------------------------------------------- W -> fp16
__global__ void wsplit_kernel(const float* __restrict__ W, int which)
{
    int i = blockIdx.x * 256 + threadIdx.x;
    g_Wh[which][i] = __float2half_rn(W[i]);
}

// ---------------------------------------------------------------- GEMM
// C[M,1024] = X @ W^T (+bias): fp16 HMMA m16n8k16.
// 128x128x64 tile, 8 warps (warp 64x32), 2-stage cp.async pipeline.
__device__ __forceinline__ void load_stage(uint32_t sbase,
                                           const __half* __restrict__ Xh,
                                           const __half* __restrict__ Wh,
                                           int bm, int bn, int k0, int tid)
{
    #pragma unroll 8
    for (int i = 0; i < 8; ++i) {
        int idx  = tid + i * 256;          // 0..2047
        int tile = idx >> 10;              // 0..1
        int r    = (idx >> 3) & 127;
        int c    = (idx & 7) * 8;          // fp16 col
        const __half* src = (tile == 0)
            ? Xh + (size_t)(bm + r) * NI + k0 + c
            : Wh + (size_t)(bn + r) * NI + k0 + c;
        uint32_t dst = sbase + tile * TILE_B + r * ROW_B + c * 2;
        asm volatile("cp.async.cg.shared.global [%0], [%1], 16;"
                     :: "r"(dst), "l"(src) : "memory");
    }
    asm volatile("cp.async.commit_group;" ::: "memory");
}

__global__ __launch_bounds__(256)
void gemm_f16_kernel(const float* __restrict__ bias, int M, int which)
{
    extern __shared__ __align__(128) char dyn[];
    const __half* __restrict__ Xh = g_Xh[which];
    const __half* __restrict__ Wh = g_Wh[which];
    float* __restrict__        H  = g_bufH[which];

    const int tid    = threadIdx.x;
    const int wid    = tid >> 5;
    const int lane   = tid & 31;
    const int warp_m = wid >> 2;           // 0..1
    const int warp_n = wid & 3;            // 0..3
    const int bn     = blockIdx.x * BN;
    const int bm     = blockIdx.y * BM;

    const uint32_t sdyn = smem_u32(dyn);

    const uint32_t laneA = (uint32_t)((lane & 15) * ROW_B + (lane >> 4) * 16);
    const uint32_t laneB = (uint32_t)(((lane & 7) + ((lane >> 4) * 8)) * ROW_B
                                      + (((lane >> 3) & 1) * 16));
    const uint32_t aWarp = (uint32_t)(warp_m * 64 * ROW_B);
    const uint32_t bWarp = (uint32_t)(warp_n * 32 * ROW_B);

    float acc[4][4][4];
    #pragma unroll
    for (int i = 0; i < 4; ++i)
        #pragma unroll
        for (int j = 0; j < 4; ++j)
            #pragma unroll
            for (int k = 0; k < 4; ++k) acc[i][j][k] = 0.f;

    load_stage(sdyn + 0 * STAGE_B, Xh, Wh, bm, bn, 0 * BK, tid);
    load_stage(sdyn + 1 * STAGE_B, Xh, Wh, bm, bn, 1 * BK, tid);

    for (int c = 0; c < NCH; ++c) {
        asm volatile("cp.async.wait_group 1;" ::: "memory");
        __syncthreads();
        const uint32_t sb = sdyn + (c & 1) * STAGE_B;

        #pragma unroll
        for (int kg = 0; kg < 4; ++kg) {
            const uint32_t kb = kg * 32;     // 16 fp16 = 32 B
            uint32_t ah[4][4], bh[2][4];
            #pragma unroll
            for (int mt = 0; mt < 4; ++mt) {
                uint32_t o = aWarp + mt * (16 * ROW_B) + laneA + kb;
                LDSM_X4(ah[mt], sb + OFF_A + o);
            }
            #pragma unroll
            for (int n2 = 0; n2 < 2; ++n2) {
                uint32_t o = bWarp + n2 * (16 * ROW_B) + laneB + kb;
                LDSM_X4(bh[n2], sb + OFF_B + o);
            }
            #pragma unroll
            for (int mt = 0; mt < 4; ++mt)
                #pragma unroll
                for (int nt = 0; nt < 4; ++nt) {
                    const int n2 = nt >> 1, ns = (nt & 1) * 2;
                    mma_f16(acc[mt][nt], ah[mt], bh[n2][ns], bh[n2][ns + 1]);
                }
        }
        __syncthreads();
        if (c + NSTG < NCH)
            load_stage(sb, Xh, Wh, bm, bn, (c + NSTG) * BK, tid);
    }

    // ---- epilogue: direct stores
    const int g  = lane >> 2;
    const int tg = lane & 3;
    #pragma unroll
    for (int mt = 0; mt < 4; ++mt) {
        int row0 = bm + warp_m * 64 + mt * 16 + g;
        #pragma unroll
        for (int nt = 0; nt < 4; ++nt) {
            int col = bn + warp_n * 32 + nt * 8 + tg * 2;
            float b0 = bias ? __ldg(&bias[col])     : 0.f;
            float b1 = bias ? __ldg(&bias[col + 1]) : 0.f;
            if (row0 < M) {
                float2 v = make_float2(acc[mt][nt][0] + b0, acc[mt][nt][1] + b1);
                *(float2*)&H[(size_t)row0 * NI + col] = v;
            }
            if (row0 + 8 < M) {
                float2 v = make_float2(acc[mt][nt][2] + b0, acc[mt][nt][3] + b1);
                *(float2*)&H[(size_t)(row0 + 8) * NI + col] = v;
            }
        }
    }
}

// ---------------------------------------------------------------- stage 5
// one warp = one node; lane = output channel. Serial register softmax.
__global__ void post_kernel(const float* __restrict__ f,
                            float* __restrict__ out,
                            int m, int N, int which)
{
    const float* __restrict__ H = g_bufH[which];
    __shared__ float sv[8][96];
    const int w    = threadIdx.x >> 5;           // warp in block (0..7)
    const int lane = threadIdx.x & 31;
    const int n    = blockIdx.x * 8 + w;
    if (n >= N) return;

    for (int i = lane; i < 32 * m; i += 32)
        sv[w][i] = f[(size_t)n * 32 * m + i];
    __syncwarp();

    float l[32];
    const float4* lp = (const float4*)&H[(size_t)n * NI + lane * 32];
    #pragma unroll
    for (int q = 0; q < 8; ++q) {
        float4 v4 = lp[q];
        l[q*4+0] = v4.x; l[q*4+1] = v4.y; l[q*4+2] = v4.z; l[q*4+3] = v4.w;
    }
    float mx = l[0];
    #pragma unroll
    for (int b = 1; b < 32; ++b) mx = fmaxf(mx, l[b]);
    float s = 0.f;
    #pragma unroll
    for (int b = 0; b < 32; ++b) { l[b] = __expf(l[b] - mx); s += l[b]; }
    float inv = 1.0f / s;

    #pragma unroll 3
    for (int c = 0; c < m; ++c) {
        float acc = 0.f;
        #pragma unroll
        for (int b = 0; b < 32; ++b) acc += l[b] * sv[w][b * m + c];
        out[((size_t)n * 32 + lane) * m + c] = acc * inv;
    }
}

// ---------------------------------------------------------------- launch
static void run_type(const float* f, void* const* prm, float* out, int N, int m,
                     int which, cudaStream_t st)
{
    const float* g1    = (const float*)prm[0];
    const float* b1    = (const float*)prm[1];
    const float* w1    = (const float*)prm[2];
    const float* g2    = (const float*)prm[3];
    const float* b2    = (const float*)prm[4];
    const float* w2    = (const float*)prm[5];
    const float* bias2 = (const float*)prm[6];

    dim3 ggrid(NI / BN, (N + BM - 1) / BM);   // n fastest -> A reuse in L2

    prep_kernel<<<N, 256, 0, st>>>(f, g1, b1, m, which);
    wsplit_kernel<<<(NI * NI) / 256, 256, 0, st>>>(w1, which);
    gemm_f16_kernel<<<ggrid, 256, DYN_SMEM, st>>>(nullptr, N, which);
    mid_ln_kernel<<<N, 256, 0, st>>>(g2, b2, which);
    wsplit_kernel<<<(NI * NI) / 256, 256, 0, st>>>(w2, which);
    gemm_f16_kernel<<<ggrid, 256, DYN_SMEM, st>>>(bias2, N, which);
    post_kernel<<<(N + 7) / 8, 256, 0, st>>>(f, out, m, N, which);
}

extern "C" void kernel_launch(void* const* d_in, const int* in_sizes, int n_in,
                              void* d_out, int out_size)
{
    // one-time resource setup (host objects only; no device memory).
    static cudaStream_t s2 = nullptr;
    static cudaEvent_t  evFork = nullptr, evJoin = nullptr;
    if (!s2) {
        cudaStreamCreateWithFlags(&s2, cudaStreamNonBlocking);
        cudaEventCreateWithFlags(&evFork, cudaEventDisableTiming);
        cudaEventCreateWithFlags(&evJoin, cudaEventDisableTiming);
        cudaFuncSetAttribute(gemm_f16_kernel,
                             cudaFuncAttributeMaxDynamicSharedMemorySize, DYN_SMEM);
    }

    const float* f0 = (const float*)d_in[0];
    const float* f1 = (const float*)d_in[1];
    int N0 = in_sizes[0] / 32;
    int N1 = in_sizes[1] / 96;
    if (N0 > MAXN) N0 = MAXN;
    if (N1 > MAXN) N1 = MAXN;
    float* out = (float*)d_out;

    // fork second chain onto s2 (graph-capturable multi-branch pattern)
    cudaEventRecord(evFork, (cudaStream_t)0);
    cudaStreamWaitEvent(s2, evFork, 0);

    run_type(f0, d_in + 2, out, N0, 1, 0, (cudaStream_t)0);
    run_type(f1, d_in + 9, out + (size_t)N0 * 32, N1, 3, 1, s2);

    // join
    cudaEventRecord(evJoin, s2);
    cudaStreamWaitEvent((cudaStream_t)0, evJoin, 0);
}